// round 16
// baseline (speedup 1.0000x reference)
#include <cuda_runtime.h>
#include <cuda_fp16.h>
#include <cstdint>

#define NFEAT 512
#define HID   128
#define NCLS  64
#define NMAX  50048
#define EMAX  640000

// ---------------- device scratch ----------------
__device__ float g_dinv[NMAX];
__device__ int   g_cnt [NMAX];
__device__ int   g_excl[NMAX];
__device__ int   g_bsum[256];
__device__ int   g_boff[256];
__device__ int   g_rs  [NMAX + 1];
__device__ int   g_cur [NMAX];
__device__ int2  g_csr [EMAX];
__device__ __half g_H1h[(size_t)NMAX * HID];
__device__ __half g_A1h[(size_t)NMAX * HID];
__device__ __half g_H2h[(size_t)NMAX * NCLS];
__device__ __half g_Bh[HID * NFEAT];
__device__ __half g_B2h[NCLS * HID];

// ==================== helpers ====================
__device__ __forceinline__ uint32_t smem_u32(const void* p) {
    uint32_t a;
    asm("{ .reg .u64 t; cvta.to.shared.u64 t, %1; cvt.u32.u64 %0, t; }"
        : "=r"(a) : "l"(p));
    return a;
}
__device__ __forceinline__ void ldm_x4(uint32_t& r0, uint32_t& r1,
                                       uint32_t& r2, uint32_t& r3, uint32_t addr) {
    asm volatile("ldmatrix.sync.aligned.m8n8.x4.shared.b16 {%0,%1,%2,%3}, [%4];"
                 : "=r"(r0), "=r"(r1), "=r"(r2), "=r"(r3) : "r"(addr));
}
__device__ __forceinline__ void mma_f16(float& d0, float& d1, float& d2, float& d3,
                                        uint32_t a0, uint32_t a1, uint32_t a2, uint32_t a3,
                                        uint32_t b0, uint32_t b1) {
    asm volatile(
        "mma.sync.aligned.m16n8k16.row.col.f32.f16.f16.f32 "
        "{%0,%1,%2,%3}, {%4,%5,%6,%7}, {%8,%9}, {%0,%1,%2,%3};"
        : "+f"(d0), "+f"(d1), "+f"(d2), "+f"(d3)
        : "r"(a0), "r"(a1), "r"(a2), "r"(a3), "r"(b0), "r"(b1));
}
__device__ __forceinline__ void cp16(uint32_t dst, const void* src) {
    asm volatile("cp.async.cg.shared.global [%0], [%1], 16;" :: "r"(dst), "l"(src));
}
#define CP_COMMIT() asm volatile("cp.async.commit_group;" ::: "memory")
#define CP_WAIT0()  asm volatile("cp.async.wait_group 0;" ::: "memory")
#define CP_WAIT1()  asm volatile("cp.async.wait_group 1;" ::: "memory")

// ==================== CSR build ====================
__global__ void k_cnt_acc(const int* __restrict__ ei, int E) {
    int e = blockIdx.x * blockDim.x + threadIdx.x;
    if (e < E) atomicAdd(&g_cnt[ei[E + e]], 1);
}
__global__ void k_scan1(int N) {
    __shared__ int sh[256];
    int i = blockIdx.x * 256 + threadIdx.x;
    int v = (i < N) ? g_cnt[i] : 0;
    if (i < N) g_dinv[i] = rsqrtf((float)(v + 1));
    sh[threadIdx.x] = v;
    __syncthreads();
    #pragma unroll
    for (int off = 1; off < 256; off <<= 1) {
        int t = (threadIdx.x >= off) ? sh[threadIdx.x - off] : 0;
        __syncthreads();
        sh[threadIdx.x] += t;
        __syncthreads();
    }
    if (i < N) g_excl[i] = sh[threadIdx.x] - v;
    if (threadIdx.x == 255) g_bsum[blockIdx.x] = sh[255];
}
__global__ void k_scan2(int nb, int N, int E) {
    __shared__ int sh[256];
    int v = (threadIdx.x < nb) ? g_bsum[threadIdx.x] : 0;
    sh[threadIdx.x] = v;
    __syncthreads();
    #pragma unroll
    for (int off = 1; off < 256; off <<= 1) {
        int t = (threadIdx.x >= off) ? sh[threadIdx.x - off] : 0;
        __syncthreads();
        sh[threadIdx.x] += t;
        __syncthreads();
    }
    if (threadIdx.x < nb) g_boff[threadIdx.x] = sh[threadIdx.x] - v;
    if (threadIdx.x == 0) g_rs[N] = E;
}
__global__ void k_scan3(int N) {
    int i = blockIdx.x * blockDim.x + threadIdx.x;
    if (i < N) {
        int r = g_excl[i] + g_boff[i >> 8];
        g_rs[i]  = r;
        g_cur[i] = r;
        g_cnt[i] = 0;
    }
}
__global__ void k_scatter(const int* __restrict__ ei, int E) {
    int e = blockIdx.x * blockDim.x + threadIdx.x;
    if (e >= E) return;
    int s = ei[e];
    int d = ei[E + e];
    int pos = atomicAdd(&g_cur[d], 1);
    g_csr[pos] = make_int2(s, __float_as_int(g_dinv[s] * g_dinv[d]));
}

// ==================== weight prep ====================
__global__ void k_prep(const float* __restrict__ W1, const float* __restrict__ W2) {
    int t = blockIdx.x * blockDim.x + threadIdx.x;
    if (t < NFEAT * HID) {
        int k = t >> 7;
        int n = t & 127;
        g_Bh[n * NFEAT + k] = __float2half_rn(W1[t]);
    } else if (t < NFEAT * HID + HID * NCLS) {
        int u = t - NFEAT * HID;
        int k = u >> 6;
        int n = u & 63;
        g_B2h[n * HID + k] = __float2half_rn(W2[u]);
    }
}

// ==================== GEMM1: triple-buffered, B prefetch depth 2 ====================
#define STRB   80
#define BUFSZ  20480
#define OFF_B  10240
#define NCHUNK (NFEAT / 32)     // 16
#define GSMEM_BYTES (3 * BUFSZ)

extern __shared__ __align__(128) unsigned char s_dyn[];

__global__ void __launch_bounds__(256, 2) k_gemm1_mma(const float* __restrict__ X, int N) {
    uint32_t sb = smem_u32(s_dyn);
    int tid  = threadIdx.x;
    int wid  = tid >> 5;
    int lane = tid & 31;
    int warp_m = (wid & 3) * 32;
    int warp_n = (wid >> 2) * 64;
    int rowBase = blockIdx.x * 128;

    float acc[2][8][4];
    #pragma unroll
    for (int mt = 0; mt < 2; mt++)
        #pragma unroll
        for (int nt = 0; nt < 8; nt++)
            #pragma unroll
            for (int j = 0; j < 4; j++) acc[mt][nt][j] = 0.0f;

    float4 xsA[4], xsB[4];
    int xrow = tid >> 3;
    int xseg = tid & 7;
    int bn   = tid >> 2;
    int bseg = tid & 3;

    #define LOAD_X(dst, c)                                                     \
        {                                                                      \
            _Pragma("unroll")                                                  \
            for (int i = 0; i < 4; i++) {                                      \
                int row = xrow + 32 * i;                                       \
                int grow = rowBase + row;                                      \
                if (grow > N - 1) grow = N - 1;                                \
                dst[i] = *(const float4*)(X + (size_t)grow * NFEAT + (c) * 32 + xseg * 4); \
            }                                                                  \
        }
    #define CP_B(c, b)                                                         \
        {                                                                      \
            _Pragma("unroll")                                                  \
            for (int i = 0; i < 2; i++) {                                      \
                int n = bn + 64 * i;                                           \
                cp16(sb + (b) * BUFSZ + OFF_B + n * STRB + bseg * 16,           \
                     g_Bh + (size_t)n * NFEAT + (c) * 32 + bseg * 8);           \
            }                                                                  \
        }
    #define STORE_A(src, b)                                                    \
        {                                                                      \
            unsigned char* base = s_dyn + (b) * BUFSZ;                         \
            _Pragma("unroll")                                                  \
            for (int i = 0; i < 4; i++) {                                      \
                int row = xrow + 32 * i;                                       \
                __half2 p0 = __floats2half2_rn(src[i].x, src[i].y);            \
                __half2 p1 = __floats2half2_rn(src[i].z, src[i].w);            \
                uint32_t off = row * STRB + xseg * 8;                          \
                *(uint2*)(base + off) =                                        \
                    make_uint2(*(uint32_t*)&p0, *(uint32_t*)&p1);              \
            }                                                                  \
        }

    // prologue: B chunks 0,1 committed; X chunks 0(smem),1,2(regs)
    CP_B(0, 0); CP_COMMIT();
    CP_B(1, 1); CP_COMMIT();
    LOAD_X(xsA, 0);
    STORE_A(xsA, 0);
    LOAD_X(xsA, 1);
    LOAD_X(xsB, 2);
    CP_WAIT1();                    // B0 complete (B1 may pend)
    __syncthreads();

    uint32_t aRowOff = (warp_m + (lane & 15)) * STRB + ((lane & 16) ? 16 : 0);
    uint32_t bRowSel = (lane & 7) + ((lane & 16) ? 8 : 0);
    uint32_t bKoff   = (lane & 8) ? 16 : 0;

    int cur = 0;
    #pragma unroll 1
    for (int c = 0; c < NCHUNK; c++) {
        int nx1 = cur + 1; if (nx1 == 3) nx1 = 0;
        int nx2 = nx1 + 1; if (nx2 == 3) nx2 = 0;

        if (c + 2 < NCHUNK) { CP_B(c + 2, nx2); CP_COMMIT(); }

        uint32_t base = sb + cur * BUFSZ;
        #pragma unroll
        for (int ka = 0; ka < 2; ka++) {
            uint32_t k0b = ka * 32;

            uint32_t a[2][4];
            #pragma unroll
            for (int mt = 0; mt < 2; mt++) {
                uint32_t aaddr = base + aRowOff + mt * (16 * STRB) + k0b;
                ldm_x4(a[mt][0], a[mt][1], a[mt][2], a[mt][3], aaddr);
            }

            uint32_t bh[8][2];
            #pragma unroll
            for (int np = 0; np < 4; np++) {
                uint32_t brow = warp_n + np * 16 + bRowSel;
                uint32_t baddr = base + OFF_B + brow * STRB + k0b + bKoff;
                ldm_x4(bh[2*np][0], bh[2*np][1], bh[2*np+1][0], bh[2*np+1][1], baddr);
            }

            #pragma unroll
            for (int mt = 0; mt < 2; mt++)
                #pragma unroll
                for (int nt = 0; nt < 8; nt++)
                    mma_f16(acc[mt][nt][0], acc[mt][nt][1], acc[mt][nt][2], acc[mt][nt][3],
                            a[mt][0], a[mt][1], a[mt][2], a[mt][3],
                            bh[nt][0], bh[nt][1]);
        }

        if (c + 1 < NCHUNK) {
            if (c & 1) {
                STORE_A(xsB, nx1);
                if (c + 3 < NCHUNK) LOAD_X(xsB, c + 3);
            } else {
                STORE_A(xsA, nx1);
                if (c + 3 < NCHUNK) LOAD_X(xsA, c + 3);
            }
            if (c + 2 < NCHUNK) { CP_WAIT1(); } else { CP_WAIT0(); }
        }
        __syncthreads();
        cur = nx1;
    }

    int r0 = rowBase + warp_m + (lane >> 2);
    int cc = warp_n + 2 * (lane & 3);
    #pragma unroll
    for (int mt = 0; mt < 2; mt++) {
        int ra = r0 + mt * 16;
        int rb = ra + 8;
        #pragma unroll
        for (int nt = 0; nt < 8; nt++) {
            int col = cc + nt * 8;
            if (ra < N)
                *(__half2*)(g_H1h + (size_t)ra * HID + col) =
                    __floats2half2_rn(acc[mt][nt][0], acc[mt][nt][1]);
            if (rb < N)
                *(__half2*)(g_H1h + (size_t)rb * HID + col) =
                    __floats2half2_rn(acc[mt][nt][2], acc[mt][nt][3]);
        }
    }
    #undef LOAD_X
    #undef CP_B
    #undef STORE_A
}

// ==================== layer-1 aggregation (warp per node, fp16 in/out) ====================
__global__ __launch_bounds__(256) void k_agg1(const float* __restrict__ b1, int N) {
    int w    = (blockIdx.x * blockDim.x + threadIdx.x) >> 5;
    int lane = threadIdx.x & 31;
    if (w >= N) return;

    float di = g_dinv[w];
    float s2 = di * di;
    float4 acc = ((const float4*)b1)[lane];
    {
        uint2 rs = *((const uint2*)(g_H1h + (size_t)w * HID) + lane);
        float2 h0 = __half22float2(*(__half2*)&rs.x);
        float2 h1 = __half22float2(*(__half2*)&rs.y);
        acc.x += s2 * h0.x; acc.y += s2 * h0.y; acc.z += s2 * h1.x; acc.w += s2 * h1.y;
    }

    int e   = g_rs[w];
    int end = g_rs[w + 1];
    #define GATH1(p, nv)                                                         \
        {                                                                        \
            uint2 rr = __ldg((const uint2*)(g_H1h + (size_t)(p).x * HID) + lane);\
            float2 q0 = __half22float2(*(__half2*)&rr.x);                        \
            float2 q1 = __half22float2(*(__half2*)&rr.y);                        \
            acc.x += (nv) * q0.x; acc.y += (nv) * q0.y;                          \
            acc.z += (nv) * q1.x; acc.w += (nv) * q1.y;                          \
        }
    for (; e + 3 < end; e += 4) {
        int2 p0 = g_csr[e];
        int2 p1 = g_csr[e + 1];
        int2 p2 = g_csr[e + 2];
        int2 p3 = g_csr[e + 3];
        GATH1(p0, __int_as_float(p0.y));
        GATH1(p1, __int_as_float(p1.y));
        GATH1(p2, __int_as_float(p2.y));
        GATH1(p3, __int_as_float(p3.y));
    }
    for (; e < end; e++) {
        int2 p0 = g_csr[e];
        GATH1(p0, __int_as_float(p0.y));
    }
    #undef GATH1

    __half2 o0 = __floats2half2_rn(fmaxf(acc.x, 0.f), fmaxf(acc.y, 0.f));
    __half2 o1 = __floats2half2_rn(fmaxf(acc.z, 0.f), fmaxf(acc.w, 0.f));
    *((uint2*)(g_A1h + (size_t)w * HID) + lane) =
        make_uint2(*(uint32_t*)&o0, *(uint32_t*)&o1);
}

// ==================== GEMM2: triple-buffered cp.async A+B ====================
#define BUF2SZ  15360
#define OFF2_B  10240
#define NCHUNK2 (HID / 32)      // 4
#define G2SMEM_BYTES (3 * BUF2SZ)

__global__ void __launch_bounds__(256) k_gemm2_mma(int N) {
    uint32_t sb = smem_u32(s_dyn);
    int tid  = threadIdx.x;
    int wid  = tid >> 5;
    int lane = tid & 31;
    int warp_m = (wid & 3) * 32;
    int warp_n = (wid >> 2) * 32;
    int rowBase = blockIdx.x * 128;

    float acc[2][4][4];
    #pragma unroll
    for (int mt = 0; mt < 2; mt++)
        #pragma unroll
        for (int nt = 0; nt < 4; nt++)
            #pragma unroll
            for (int j = 0; j < 4; j++) acc[mt][nt][j] = 0.0f;

    int arow = tid >> 1;
    int aseg = (tid & 1) * 2;
    int bn   = tid >> 2;
    int bseg = tid & 3;

    #define CP_A2(c, b)                                                        \
        {                                                                      \
            int grow = rowBase + arow;                                         \
            if (grow > N - 1) grow = N - 1;                                    \
            const __half* srcp = g_A1h + (size_t)grow * HID + (c) * 32;        \
            uint32_t dst = sb + (b) * BUF2SZ + arow * STRB;                    \
            cp16(dst + aseg * 16,       srcp + aseg * 8);                      \
            cp16(dst + (aseg + 1) * 16, srcp + (aseg + 1) * 8);                \
        }
    #define CP_B2(c, b)                                                        \
        {                                                                      \
            cp16(sb + (b) * BUF2SZ + OFF2_B + bn * STRB + bseg * 16,            \
                 g_B2h + (size_t)bn * HID + (c) * 32 + bseg * 8);               \
        }

    CP_A2(0, 0); CP_B2(0, 0); CP_COMMIT();
    CP_A2(1, 1); CP_B2(1, 1); CP_COMMIT();
    CP_WAIT1();
    __syncthreads();

    uint32_t aRowOff = (warp_m + (lane & 15)) * STRB + ((lane & 16) ? 16 : 0);
    uint32_t bRowSel = (lane & 7) + ((lane & 16) ? 8 : 0);
    uint32_t bKoff   = (lane & 8) ? 16 : 0;

    int cur = 0;
    #pragma unroll 1
    for (int c = 0; c < NCHUNK2; c++) {
        int nx1 = cur + 1; if (nx1 == 3) nx1 = 0;
        int nx2 = nx1 + 1; if (nx2 == 3) nx2 = 0;

        if (c + 2 < NCHUNK2) { CP_A2(c + 2, nx2); CP_B2(c + 2, nx2); CP_COMMIT(); }

        uint32_t base = sb + cur * BUF2SZ;
        #pragma unroll
        for (int ka = 0; ka < 2; ka++) {
            uint32_t k0b = ka * 32;

            uint32_t a[2][4];
            #pragma unroll
            for (int mt = 0; mt < 2; mt++) {
                uint32_t aaddr = base + aRowOff + mt * (16 * STRB) + k0b;
                ldm_x4(a[mt][0], a[mt][1], a[mt][2], a[mt][3], aaddr);
            }

            uint32_t bh[4][2];
            #pragma unroll
            for (int np = 0; np < 2; np++) {
                uint32_t brow = warp_n + np * 16 + bRowSel;
                uint32_t baddr = base + OFF2_B + brow * STRB + k0b + bKoff;
                ldm_x4(bh[2*np][0], bh[2*np][1], bh[2*np+1][0], bh[2*np+1][1], baddr);
            }

            #pragma unroll
            for (int mt = 0; mt < 2; mt++)
                #pragma unroll
                for (int nt = 0; nt < 4; nt++)
                    mma_f16(acc[mt][nt][0], acc[mt][nt][1], acc[mt][nt][2], acc[mt][nt][3],
                            a[mt][0], a[mt][1], a[mt][2], a[mt][3],
                            bh[nt][0], bh[nt][1]);
        }

        if (c + 1 < NCHUNK2) {
            if (c + 2 < NCHUNK2) { CP_WAIT1(); } else { CP_WAIT0(); }
        }
        __syncthreads();
        cur = nx1;
    }

    int r0 = rowBase + warp_m + (lane >> 2);
    int cc = warp_n + 2 * (lane & 3);
    #pragma unroll
    for (int mt = 0; mt < 2; mt++) {
        int ra = r0 + mt * 16;
        int rb = ra + 8;
        #pragma unroll
        for (int nt = 0; nt < 4; nt++) {
            int col = cc + nt * 8;
            if (ra < N)
                *(__half2*)(g_H2h + (size_t)ra * NCLS + col) =
                    __floats2half2_rn(acc[mt][nt][0], acc[mt][nt][1]);
            if (rb < N)
                *(__half2*)(g_H2h + (size_t)rb * NCLS + col) =
                    __floats2half2_rn(acc[mt][nt][2], acc[mt][nt][3]);
        }
    }
    #undef CP_A2
    #undef CP_B2
}

// ==================== layer-2 aggregation (16 lanes per node, fp16 gather) ====================
__global__ __launch_bounds__(256) void k_agg2(const float* __restrict__ b2,
                                              float* __restrict__ out, int N) {
    int t = blockIdx.x * blockDim.x + threadIdx.x;
    int i = t >> 4;
    int c = t & 15;
    if (i >= N) return;

    float di = g_dinv[i];
    float s2 = di * di;
    float4 acc = ((const float4*)b2)[c];
    {
        uint2 rs = *((const uint2*)(g_H2h + (size_t)i * NCLS) + c);
        float2 h0 = __half22float2(*(__half2*)&rs.x);
        float2 h1 = __half22float2(*(__half2*)&rs.y);
        acc.x += s2 * h0.x; acc.y += s2 * h0.y; acc.z += s2 * h1.x; acc.w += s2 * h1.y;
    }

    int e   = g_rs[i];
    int end = g_rs[i + 1];
    #define GATH2(p, nv)                                                         \
        {                                                                        \
            uint2 rr = __ldg((const uint2*)(g_H2h + (size_t)(p).x * NCLS) + c);  \
            float2 q0 = __half22float2(*(__half2*)&rr.x);                        \
            float2 q1 = __half22float2(*(__half2*)&rr.y);                        \
            acc.x += (nv) * q0.x; acc.y += (nv) * q0.y;                          \
            acc.z += (nv) * q1.x; acc.w += (nv) * q1.y;                          \
        }
    for (; e + 3 < end; e += 4) {
        int2 p0 = g_csr[e];
        int2 p1 = g_csr[e + 1];
        int2 p2 = g_csr[e + 2];
        int2 p3 = g_csr[e + 3];
        GATH2(p0, __int_as_float(p0.y));
        GATH2(p1, __int_as_float(p1.y));
        GATH2(p2, __int_as_float(p2.y));
        GATH2(p3, __int_as_float(p3.y));
    }
    for (; e < end; e++) {
        int2 p0 = g_csr[e];
        GATH2(p0, __int_as_float(p0.y));
    }
    #undef GATH2

    *((float4*)(out + (size_t)i * NCLS) + c) = acc;
}

// ==================== launch ====================
struct AuxObjs {
    cudaStream_t s1;
    cudaEvent_t  e0, e1;
    AuxObjs() {
        cudaStreamCreateWithFlags(&s1, cudaStreamNonBlocking);
        cudaEventCreateWithFlags(&e0, cudaEventDisableTiming);
        cudaEventCreateWithFlags(&e1, cudaEventDisableTiming);
    }
};

extern "C" void kernel_launch(void* const* d_in, const int* in_sizes, int n_in,
                              void* d_out, int out_size) {
    static AuxObjs aux;

    const float* x  = (const float*)d_in[0];
    const int*   ei = (const int*)  d_in[1];
    const float* W1 = (const float*)d_in[2];
    const float* b1 = (const float*)d_in[3];
    const float* W2 = (const float*)d_in[4];
    const float* b2 = (const float*)d_in[5];
    float* out = (float*)d_out;

    int N = in_sizes[0] / NFEAT;   // 50000
    int E = in_sizes[1] / 2;       // 640000
    int nb = (N + 255) / 256;

    cudaFuncSetAttribute(k_gemm1_mma, cudaFuncAttributeMaxDynamicSharedMemorySize,
                         GSMEM_BYTES);
    cudaFuncSetAttribute(k_gemm2_mma, cudaFuncAttributeMaxDynamicSharedMemorySize,
                         G2SMEM_BYTES);

    // Fork CSR branch onto s1.
    cudaEventRecord(aux.e0, 0);
    cudaStreamWaitEvent(aux.s1, aux.e0, 0);

    k_cnt_acc <<<(E + 255) / 256, 256, 0, aux.s1>>>(ei, E);              // 1
    k_prep    <<<(NFEAT * HID + HID * NCLS + 255) / 256, 256>>>(W1, W2); // 2 (main)
    k_gemm1_mma<<<(N + 127) / 128, 256, GSMEM_BYTES>>>(x, N);            // 3 (main)
    k_scan1   <<<nb, 256, 0, aux.s1>>>(N);                               // 4
    k_scan2   <<<1, 256, 0, aux.s1>>>(nb, N, E);                         // 5
    k_scan3   <<<nb, 256, 0, aux.s1>>>(N);                               // 6
    k_scatter <<<(E + 255) / 256, 256, 0, aux.s1>>>(ei, E);              // 7
    cudaEventRecord(aux.e1, aux.s1);
    cudaStreamWaitEvent(0, aux.e1, 0);

    k_agg1     <<<(N * 32 + 255) / 256, 256>>>(b1, N);                   // 8
    k_gemm2_mma<<<(N + 127) / 128, 256, G2SMEM_BYTES>>>(N);              // 9
    k_agg2     <<<(N * 16 + 255) / 256, 256>>>(b2, out, N);              // 10
}

// round 17
// speedup vs baseline: 1.0268x; 1.0268x over previous
#include <cuda_runtime.h>
#include <cuda_fp16.h>
#include <cstdint>

#define NFEAT 512
#define HID   128
#define NCLS  64
#define NMAX  50048
#define EMAX  640000

// ---------------- device scratch ----------------
__device__ float g_dinv[NMAX];
__device__ int   g_cnt [NMAX];          // zero-init at load; re-zeroed by k_scan3
__device__ int   g_excl[NMAX];
__device__ int   g_bsum[256];
__device__ int   g_boff[256];
__device__ int   g_rs  [NMAX + 1];
__device__ int   g_cur [NMAX];
__device__ int2  g_csr [EMAX];
__device__ __half g_H1h[(size_t)NMAX * HID];   // layer-1 pre-agg (fp16)
__device__ __half g_A1h[(size_t)NMAX * HID];   // layer-1 post-agg (fp16)
__device__ __half g_H2h[(size_t)NMAX * NCLS];  // layer-2 pre-agg (fp16)
__device__ __half g_Bh[HID * NFEAT];    // W1 fp16, transposed [n][k]
__device__ __half g_B2h[NCLS * HID];    // W2 fp16, transposed [n][k]

// ==================== helpers ====================
__device__ __forceinline__ uint32_t smem_u32(const void* p) {
    uint32_t a;
    asm("{ .reg .u64 t; cvta.to.shared.u64 t, %1; cvt.u32.u64 %0, t; }"
        : "=r"(a) : "l"(p));
    return a;
}
__device__ __forceinline__ void ldm_x4(uint32_t& r0, uint32_t& r1,
                                       uint32_t& r2, uint32_t& r3, uint32_t addr) {
    asm volatile("ldmatrix.sync.aligned.m8n8.x4.shared.b16 {%0,%1,%2,%3}, [%4];"
                 : "=r"(r0), "=r"(r1), "=r"(r2), "=r"(r3) : "r"(addr));
}
__device__ __forceinline__ void mma_f16(float& d0, float& d1, float& d2, float& d3,
                                        uint32_t a0, uint32_t a1, uint32_t a2, uint32_t a3,
                                        uint32_t b0, uint32_t b1) {
    asm volatile(
        "mma.sync.aligned.m16n8k16.row.col.f32.f16.f16.f32 "
        "{%0,%1,%2,%3}, {%4,%5,%6,%7}, {%8,%9}, {%0,%1,%2,%3};"
        : "+f"(d0), "+f"(d1), "+f"(d2), "+f"(d3)
        : "r"(a0), "r"(a1), "r"(a2), "r"(a3), "r"(b0), "r"(b1));
}
__device__ __forceinline__ void cp16(uint32_t dst, const void* src) {
    asm volatile("cp.async.cg.shared.global [%0], [%1], 16;" :: "r"(dst), "l"(src));
}
#define CP_COMMIT() asm volatile("cp.async.commit_group;" ::: "memory")
#define CP_WAIT0()  asm volatile("cp.async.wait_group 0;" ::: "memory")

// ==================== CSR build ====================
__global__ void k_cnt_acc(const int* __restrict__ ei, int E) {
    int e = blockIdx.x * blockDim.x + threadIdx.x;
    if (e < E) atomicAdd(&g_cnt[ei[E + e]], 1);
}
__global__ void k_scan1(int N) {
    __shared__ int sh[256];
    int i = blockIdx.x * 256 + threadIdx.x;
    int v = (i < N) ? g_cnt[i] : 0;
    if (i < N) g_dinv[i] = rsqrtf((float)(v + 1));
    sh[threadIdx.x] = v;
    __syncthreads();
    #pragma unroll
    for (int off = 1; off < 256; off <<= 1) {
        int t = (threadIdx.x >= off) ? sh[threadIdx.x - off] : 0;
        __syncthreads();
        sh[threadIdx.x] += t;
        __syncthreads();
    }
    if (i < N) g_excl[i] = sh[threadIdx.x] - v;
    if (threadIdx.x == 255) g_bsum[blockIdx.x] = sh[255];
}
__global__ void k_scan2(int nb, int N, int E) {
    __shared__ int sh[256];
    int v = (threadIdx.x < nb) ? g_bsum[threadIdx.x] : 0;
    sh[threadIdx.x] = v;
    __syncthreads();
    #pragma unroll
    for (int off = 1; off < 256; off <<= 1) {
        int t = (threadIdx.x >= off) ? sh[threadIdx.x - off] : 0;
        __syncthreads();
        sh[threadIdx.x] += t;
        __syncthreads();
    }
    if (threadIdx.x < nb) g_boff[threadIdx.x] = sh[threadIdx.x] - v;
    if (threadIdx.x == 0) g_rs[N] = E;
}
__global__ void k_scan3(int N) {
    int i = blockIdx.x * blockDim.x + threadIdx.x;
    if (i < N) {
        int r = g_excl[i] + g_boff[i >> 8];
        g_rs[i]  = r;
        g_cur[i] = r;
        g_cnt[i] = 0;
    }
}
__global__ void k_scatter(const int* __restrict__ ei, int E) {
    int e = blockIdx.x * blockDim.x + threadIdx.x;
    if (e >= E) return;
    int s = ei[e];
    int d = ei[E + e];
    int pos = atomicAdd(&g_cur[d], 1);
    g_csr[pos] = make_int2(s, __float_as_int(g_dinv[s] * g_dinv[d]));
}

// ==================== weight prep (split: W1 on critical path, W2 hidden) ====================
__global__ void k_prepW1(const float* __restrict__ W1) {
    int t = blockIdx.x * blockDim.x + threadIdx.x;
    if (t < NFEAT * HID) {
        int k = t >> 7;
        int n = t & 127;
        g_Bh[n * NFEAT + k] = __float2half_rn(W1[t]);
    }
}
__global__ void k_prepW2(const float* __restrict__ W2) {
    int t = blockIdx.x * blockDim.x + threadIdx.x;
    if (t < HID * NCLS) {
        int k = t >> 6;
        int n = t & 63;
        g_B2h[n * HID + k] = __float2half_rn(W2[t]);
    }
}

// ==================== GEMM1: fp16(X) @ fp16(W1), 1 MMA, X prefetch depth 2 (R15) ====================
#define STRB   80
#define BUFSZ  20480
#define OFF_B  10240
#define NCHUNK (NFEAT / 32)     // 16
#define GSMEM_BYTES (2 * BUFSZ)

extern __shared__ __align__(128) unsigned char s_dyn[];

__global__ void __launch_bounds__(256, 2) k_gemm1_mma(const float* __restrict__ X, int N) {
    uint32_t sb = smem_u32(s_dyn);
    int tid  = threadIdx.x;
    int wid  = tid >> 5;
    int lane = tid & 31;
    int warp_m = (wid & 3) * 32;
    int warp_n = (wid >> 2) * 64;
    int rowBase = blockIdx.x * 128;

    float acc[2][8][4];
    #pragma unroll
    for (int mt = 0; mt < 2; mt++)
        #pragma unroll
        for (int nt = 0; nt < 8; nt++)
            #pragma unroll
            for (int j = 0; j < 4; j++) acc[mt][nt][j] = 0.0f;

    float4 xsA[4], xsB[4];
    int xrow = tid >> 3;
    int xseg = tid & 7;
    int bn   = tid >> 2;
    int bseg = tid & 3;

    #define LOAD_X(dst, c)                                                     \
        {                                                                      \
            _Pragma("unroll")                                                  \
            for (int i = 0; i < 4; i++) {                                      \
                int row = xrow + 32 * i;                                       \
                int grow = rowBase + row;                                      \
                if (grow > N - 1) grow = N - 1;                                \
                dst[i] = *(const float4*)(X + (size_t)grow * NFEAT + (c) * 32 + xseg * 4); \
            }                                                                  \
        }
    #define CP_B(c, b)                                                         \
        {                                                                      \
            _Pragma("unroll")                                                  \
            for (int i = 0; i < 2; i++) {                                      \
                int n = bn + 64 * i;                                           \
                cp16(sb + (b) * BUFSZ + OFF_B + n * STRB + bseg * 16,           \
                     g_Bh + (size_t)n * NFEAT + (c) * 32 + bseg * 8);           \
            }                                                                  \
        }
    #define STORE_A(src, b)                                                    \
        {                                                                      \
            unsigned char* base = s_dyn + (b) * BUFSZ;                         \
            _Pragma("unroll")                                                  \
            for (int i = 0; i < 4; i++) {                                      \
                int row = xrow + 32 * i;                                       \
                __half2 p0 = __floats2half2_rn(src[i].x, src[i].y);            \
                __half2 p1 = __floats2half2_rn(src[i].z, src[i].w);            \
                uint32_t off = row * STRB + xseg * 8;                          \
                *(uint2*)(base + off) =                                        \
                    make_uint2(*(uint32_t*)&p0, *(uint32_t*)&p1);              \
            }                                                                  \
        }

    CP_B(0, 0); CP_COMMIT();
    LOAD_X(xsA, 0);
    STORE_A(xsA, 0);
    LOAD_X(xsA, 1);
    LOAD_X(xsB, 2);
    CP_WAIT0();
    __syncthreads();

    uint32_t aRowOff = (warp_m + (lane & 15)) * STRB + ((lane & 16) ? 16 : 0);
    uint32_t bRowSel = (lane & 7) + ((lane & 16) ? 8 : 0);
    uint32_t bKoff   = (lane & 8) ? 16 : 0;

    #pragma unroll 1
    for (int c = 0; c < NCHUNK; c++) {
        int cur = c & 1;
        if (c + 1 < NCHUNK) { CP_B(c + 1, cur ^ 1); CP_COMMIT(); }

        uint32_t base = sb + cur * BUFSZ;
        #pragma unroll
        for (int ka = 0; ka < 2; ka++) {
            uint32_t k0b = ka * 32;

            uint32_t a[2][4];
            #pragma unroll
            for (int mt = 0; mt < 2; mt++) {
                uint32_t aaddr = base + aRowOff + mt * (16 * STRB) + k0b;
                ldm_x4(a[mt][0], a[mt][1], a[mt][2], a[mt][3], aaddr);
            }

            uint32_t bh[8][2];
            #pragma unroll
            for (int np = 0; np < 4; np++) {
                uint32_t brow = warp_n + np * 16 + bRowSel;
                uint32_t baddr = base + OFF_B + brow * STRB + k0b + bKoff;
                ldm_x4(bh[2*np][0], bh[2*np][1], bh[2*np+1][0], bh[2*np+1][1], baddr);
            }

            #pragma unroll
            for (int mt = 0; mt < 2; mt++)
                #pragma unroll
                for (int nt = 0; nt < 8; nt++)
                    mma_f16(acc[mt][nt][0], acc[mt][nt][1], acc[mt][nt][2], acc[mt][nt][3],
                            a[mt][0], a[mt][1], a[mt][2], a[mt][3],
                            bh[nt][0], bh[nt][1]);
        }

        if (c + 1 < NCHUNK) {
            if (c & 1) {
                STORE_A(xsB, cur ^ 1);
                if (c + 3 < NCHUNK) LOAD_X(xsB, c + 3);
            } else {
                STORE_A(xsA, cur ^ 1);
                if (c + 3 < NCHUNK) LOAD_X(xsA, c + 3);
            }
            CP_WAIT0();
        }
        __syncthreads();
    }

    int r0 = rowBase + warp_m + (lane >> 2);
    int cc = warp_n + 2 * (lane & 3);
    #pragma unroll
    for (int mt = 0; mt < 2; mt++) {
        int ra = r0 + mt * 16;
        int rb = ra + 8;
        #pragma unroll
        for (int nt = 0; nt < 8; nt++) {
            int col = cc + nt * 8;
            if (ra < N)
                *(__half2*)(g_H1h + (size_t)ra * HID + col) =
                    __floats2half2_rn(acc[mt][nt][0], acc[mt][nt][1]);
            if (rb < N)
                *(__half2*)(g_H1h + (size_t)rb * HID + col) =
                    __floats2half2_rn(acc[mt][nt][2], acc[mt][nt][3]);
        }
    }
    #undef LOAD_X
    #undef CP_B
    #undef STORE_A
}

// ==================== layer-1 aggregation (warp per node, fp16 in/out — R15) ====================
__global__ __launch_bounds__(256) void k_agg1(const float* __restrict__ b1, int N) {
    int w    = (blockIdx.x * blockDim.x + threadIdx.x) >> 5;
    int lane = threadIdx.x & 31;
    if (w >= N) return;

    float di = g_dinv[w];
    float s2 = di * di;
    float4 acc = ((const float4*)b1)[lane];
    {
        uint2 rs = *((const uint2*)(g_H1h + (size_t)w * HID) + lane);
        float2 h0 = __half22float2(*(__half2*)&rs.x);
        float2 h1 = __half22float2(*(__half2*)&rs.y);
        acc.x += s2 * h0.x; acc.y += s2 * h0.y; acc.z += s2 * h1.x; acc.w += s2 * h1.y;
    }

    int e   = g_rs[w];
    int end = g_rs[w + 1];
    #define GATH1(p, nv)                                                         \
        {                                                                        \
            uint2 rr = __ldg((const uint2*)(g_H1h + (size_t)(p).x * HID) + lane);\
            float2 q0 = __half22float2(*(__half2*)&rr.x);                        \
            float2 q1 = __half22float2(*(__half2*)&rr.y);                        \
            acc.x += (nv) * q0.x; acc.y += (nv) * q0.y;                          \
            acc.z += (nv) * q1.x; acc.w += (nv) * q1.y;                          \
        }
    for (; e + 3 < end; e += 4) {
        int2 p0 = g_csr[e];
        int2 p1 = g_csr[e + 1];
        int2 p2 = g_csr[e + 2];
        int2 p3 = g_csr[e + 3];
        GATH1(p0, __int_as_float(p0.y));
        GATH1(p1, __int_as_float(p1.y));
        GATH1(p2, __int_as_float(p2.y));
        GATH1(p3, __int_as_float(p3.y));
    }
    for (; e < end; e++) {
        int2 p0 = g_csr[e];
        GATH1(p0, __int_as_float(p0.y));
    }
    #undef GATH1

    __half2 o0 = __floats2half2_rn(fmaxf(acc.x, 0.f), fmaxf(acc.y, 0.f));
    __half2 o1 = __floats2half2_rn(fmaxf(acc.z, 0.f), fmaxf(acc.w, 0.f));
    *((uint2*)(g_A1h + (size_t)w * HID) + lane) =
        make_uint2(*(uint32_t*)&o0, *(uint32_t*)&o1);
}

// ==================== GEMM2: fp16 A via cp.async, 1 MMA (R15) ====================
#define BUF2SZ  15360
#define OFF2_B  10240
#define NCHUNK2 (HID / 32)      // 4
#define G2SMEM_BYTES (2 * BUF2SZ)

__global__ void __launch_bounds__(256) k_gemm2_mma(int N) {
    uint32_t sb = smem_u32(s_dyn);
    int tid  = threadIdx.x;
    int wid  = tid >> 5;
    int lane = tid & 31;
    int warp_m = (wid & 3) * 32;
    int warp_n = (wid >> 2) * 32;
    int rowBase = blockIdx.x * 128;

    float acc[2][4][4];
    #pragma unroll
    for (int mt = 0; mt < 2; mt++)
        #pragma unroll
        for (int nt = 0; nt < 4; nt++)
            #pragma unroll
            for (int j = 0; j < 4; j++) acc[mt][nt][j] = 0.0f;

    int arow = tid >> 1;
    int aseg = (tid & 1) * 2;
    int bn   = tid >> 2;
    int bseg = tid & 3;

    #define CP_A2(c, b)                                                        \
        {                                                                      \
            int grow = rowBase + arow;                                         \
            if (grow > N - 1) grow = N - 1;                                    \
            const __half* srcp = g_A1h + (size_t)grow * HID + (c) * 32;        \
            uint32_t dst = sb + (b) * BUF2SZ + arow * STRB;                    \
            cp16(dst + aseg * 16,       srcp + aseg * 8);                      \
            cp16(dst + (aseg + 1) * 16, srcp + (aseg + 1) * 8);                \
        }
    #define CP_B2(c, b)                                                        \
        {                                                                      \
            cp16(sb + (b) * BUF2SZ + OFF2_B + bn * STRB + bseg * 16,            \
                 g_B2h + (size_t)bn * HID + (c) * 32 + bseg * 8);               \
        }

    CP_A2(0, 0); CP_B2(0, 0); CP_COMMIT();
    CP_WAIT0();
    __syncthreads();

    uint32_t aRowOff = (warp_m + (lane & 15)) * STRB + ((lane & 16) ? 16 : 0);
    uint32_t bRowSel = (lane & 7) + ((lane & 16) ? 8 : 0);
    uint32_t bKoff   = (lane & 8) ? 16 : 0;

    #pragma unroll 1
    for (int c = 0; c < NCHUNK2; c++) {
        int cur = c & 1;
        if (c + 1 < NCHUNK2) {
            CP_A2(c + 1, cur ^ 1);
            CP_B2(c + 1, cur ^ 1);
            CP_COMMIT();
        }

        uint32_t base = sb + cur * BUF2SZ;
        #pragma unroll
        for (int ka = 0; ka < 2; ka++) {
            uint32_t k0b = ka * 32;

            uint32_t a[2][4];
            #pragma unroll
            for (int mt = 0; mt < 2; mt++) {
                uint32_t aaddr = base + aRowOff + mt * (16 * STRB) + k0b;
                ldm_x4(a[mt][0], a[mt][1], a[mt][2], a[mt][3], aaddr);
            }

            uint32_t bh[4][2];
            #pragma unroll
            for (int np = 0; np < 2; np++) {
                uint32_t brow = warp_n + np * 16 + bRowSel;
                uint32_t baddr = base + OFF2_B + brow * STRB + k0b + bKoff;
                ldm_x4(bh[2*np][0], bh[2*np][1], bh[2*np+1][0], bh[2*np+1][1], baddr);
            }

            #pragma unroll
            for (int mt = 0; mt < 2; mt++)
                #pragma unroll
                for (int nt = 0; nt < 4; nt++)
                    mma_f16(acc[mt][nt][0], acc[mt][nt][1], acc[mt][nt][2], acc[mt][nt][3],
                            a[mt][0], a[mt][1], a[mt][2], a[mt][3],
                            bh[nt][0], bh[nt][1]);
        }

        if (c + 1 < NCHUNK2) CP_WAIT0();
        __syncthreads();
    }

    int r0 = rowBase + warp_m + (lane >> 2);
    int cc = warp_n + 2 * (lane & 3);
    #pragma unroll
    for (int mt = 0; mt < 2; mt++) {
        int ra = r0 + mt * 16;
        int rb = ra + 8;
        #pragma unroll
        for (int nt = 0; nt < 4; nt++) {
            int col = cc + nt * 8;
            if (ra < N)
                *(__half2*)(g_H2h + (size_t)ra * NCLS + col) =
                    __floats2half2_rn(acc[mt][nt][0], acc[mt][nt][1]);
            if (rb < N)
                *(__half2*)(g_H2h + (size_t)rb * NCLS + col) =
                    __floats2half2_rn(acc[mt][nt][2], acc[mt][nt][3]);
        }
    }
    #undef CP_A2
    #undef CP_B2
}

// ==================== layer-2 aggregation (16 lanes per node, fp16 gather — R15) ====================
__global__ __launch_bounds__(256) void k_agg2(const float* __restrict__ b2,
                                              float* __restrict__ out, int N) {
    int t = blockIdx.x * blockDim.x + threadIdx.x;
    int i = t >> 4;
    int c = t & 15;
    if (i >= N) return;

    float di = g_dinv[i];
    float s2 = di * di;
    float4 acc = ((const float4*)b2)[c];
    {
        uint2 rs = *((const uint2*)(g_H2h + (size_t)i * NCLS) + c);
        float2 h0 = __half22float2(*(__half2*)&rs.x);
        float2 h1 = __half22float2(*(__half2*)&rs.y);
        acc.x += s2 * h0.x; acc.y += s2 * h0.y; acc.z += s2 * h1.x; acc.w += s2 * h1.y;
    }

    int e   = g_rs[i];
    int end = g_rs[i + 1];
    #define GATH2(p, nv)                                                         \
        {                                                                        \
            uint2 rr = __ldg((const uint2*)(g_H2h + (size_t)(p).x * NCLS) + c);  \
            float2 q0 = __half22float2(*(__half2*)&rr.x);                        \
            float2 q1 = __half22float2(*(__half2*)&rr.y);                        \
            acc.x += (nv) * q0.x; acc.y += (nv) * q0.y;                          \
            acc.z += (nv) * q1.x; acc.w += (nv) * q1.y;                          \
        }
    for (; e + 3 < end; e += 4) {
        int2 p0 = g_csr[e];
        int2 p1 = g_csr[e + 1];
        int2 p2 = g_csr[e + 2];
        int2 p3 = g_csr[e + 3];
        GATH2(p0, __int_as_float(p0.y));
        GATH2(p1, __int_as_float(p1.y));
        GATH2(p2, __int_as_float(p2.y));
        GATH2(p3, __int_as_float(p3.y));
    }
    for (; e < end; e++) {
        int2 p0 = g_csr[e];
        GATH2(p0, __int_as_float(p0.y));
    }
    #undef GATH2

    *((float4*)(out + (size_t)i * NCLS) + c) = acc;
}

// ==================== launch ====================
struct AuxObjs {
    cudaStream_t s1;
    cudaEvent_t  e0, e1;
    AuxObjs() {
        cudaStreamCreateWithFlags(&s1, cudaStreamNonBlocking);
        cudaEventCreateWithFlags(&e0, cudaEventDisableTiming);
        cudaEventCreateWithFlags(&e1, cudaEventDisableTiming);
    }
};

extern "C" void kernel_launch(void* const* d_in, const int* in_sizes, int n_in,
                              void* d_out, int out_size) {
    static AuxObjs aux;

    const float* x  = (const float*)d_in[0];
    const int*   ei = (const int*)  d_in[1];
    const float* W1 = (const float*)d_in[2];
    const float* b1 = (const float*)d_in[3];
    const float* W2 = (const float*)d_in[4];
    const float* b2 = (const float*)d_in[5];
    float* out = (float*)d_out;

    int N = in_sizes[0] / NFEAT;   // 50000
    int E = in_sizes[1] / 2;       // 640000
    int nb = (N + 255) / 256;

    cudaFuncSetAttribute(k_gemm1_mma, cudaFuncAttributeMaxDynamicSharedMemorySize,
                         GSMEM_BYTES);
    cudaFuncSetAttribute(k_gemm2_mma, cudaFuncAttributeMaxDynamicSharedMemorySize,
                         G2SMEM_BYTES);

    // Fork CSR + W2-prep branch onto s1.
    cudaEventRecord(aux.e0, 0);
    cudaStreamWaitEvent(aux.s1, aux.e0, 0);

    // --- main stream: W1 prep -> gemm1 (critical path) ---
    k_prepW1<<<(NFEAT * HID + 255) / 256, 256>>>(W1);
    k_gemm1_mma<<<(N + 127) / 128, 256, GSMEM_BYTES>>>(x, N);

    // --- s1: CSR build + W2 prep (hidden under gemm1) ---
    k_cnt_acc <<<(E + 255) / 256, 256, 0, aux.s1>>>(ei, E);
    k_prepW2  <<<(HID * NCLS + 255) / 256, 256, 0, aux.s1>>>(W2);
    k_scan1   <<<nb, 256, 0, aux.s1>>>(N);
    k_scan2   <<<1, 256, 0, aux.s1>>>(nb, N, E);
    k_scan3   <<<nb, 256, 0, aux.s1>>>(N);
    k_scatter <<<(E + 255) / 256, 256, 0, aux.s1>>>(ei, E);
    cudaEventRecord(aux.e1, aux.s1);
    cudaStreamWaitEvent(0, aux.e1, 0);

    k_agg1     <<<(N * 32 + 255) / 256, 256>>>(b1, N);
    k_gemm2_mma<<<(N + 127) / 128, 256, G2SMEM_BYTES>>>(N);
    k_agg2     <<<(N * 16 + 255) / 256, 256>>>(b2, out, N);
}